// round 1
// baseline (speedup 1.0000x reference)
#include <cuda_runtime.h>
#include <cstdint>

// Problem constants
#define BB 8
#define HH 256
#define WW 256
#define CC 32     // in channels = out channels
#define KK 16     // kept rfft bins along W
// h-mode set: {0..15} U {240..255} -> 32 modes, paired as (m, 256-m)

// Scratch (static device allocations are allowed)
__device__ float2 g_X1[BB * KK * HH * CC];   // [b][k][y][c]  fwd W-DFT result
__device__ float2 g_G [BB * HH * KK * CC];   // [b][y][k][o]  scaled spectral rows for inverse W
__device__ float2 g_Wt[KK * 32 * CC * CC];   // [k][h'][c][o] reordered complex weights

// ---------------------------------------------------------------------------
// Kernel 0: reorder weights  w_real/w_imag[w][i][o][m1][m2] -> Wt[k][h'][c][o]
//   h' = w*16 + m1, k = m2, c = i
// ---------------------------------------------------------------------------
__global__ void k0_reorder_w(const float* __restrict__ wr, const float* __restrict__ wi) {
    int idx = blockIdx.x * 256 + threadIdx.x;          // 0 .. 524287
    int o  = idx & 31;
    int c  = (idx >> 5) & 31;
    int hp = (idx >> 10) & 31;
    int k  = idx >> 15;
    int w  = hp >> 4;
    int m1 = hp & 15;
    int src = (((w * 32 + c) * 32 + o) * 16 + m1) * 16 + k;
    g_Wt[idx] = make_float2(wr[src], wi[src]);
}

// ---------------------------------------------------------------------------
// Kernel 1: forward W-DFT per (b,y) row.
//   X1[b,k,y,c] = sum_x x[b,y,x,c] * e^{-2*pi*i*k*x/256},  k = 0..15
//   Symmetry: s_x = v_x + v_{256-x}, d_x = v_x - v_{256-x}:
//     re = v0 + (-1)^k v128 + sum_{x=1..127} s_x cos(kx)
//     im =                  - sum_{x=1..127} d_x sin(kx)
// ---------------------------------------------------------------------------
__global__ void k1_fwd_w(const float* __restrict__ x) {
    __shared__ float xs[HH * CC];        // 32 KB
    __shared__ float ctab[256], stab[256];
    int t = threadIdx.x;
    int bid = blockIdx.x;                // b*256 + y

    {
        float ang = 6.28318530717958647692f * (float)t / 256.0f;
        float s, c0;
        sincosf(ang, &s, &c0);
        ctab[t] = c0; stab[t] = s;
    }

    // load row tile [256 x][32 c], coalesced float4
    const float4* xin = (const float4*)(x + (size_t)bid * (WW * CC));
    float4* xs4 = (float4*)xs;
#pragma unroll
    for (int i = t; i < (WW * CC) / 4; i += 256) xs4[i] = xin[i];
    __syncthreads();

    // in-place sum/diff: xs[x'] <- s, xs[256-x'] <- d   (x' = 1..127)
    for (int tt = t; tt < 127 * 32; tt += 256) {
        int xp = (tt >> 5) + 1, c = tt & 31;
        float a = xs[xp * 32 + c];
        float b = xs[(256 - xp) * 32 + c];
        xs[xp * 32 + c]        = a + b;
        xs[(256 - xp) * 32 + c] = a - b;
    }
    __syncthreads();

    int c  = t & 31;
    int k1 = t >> 5;        // 0..7  (warp-uniform)
    int k2 = k1 + 8;

    float v0   = xs[c];
    float v128 = xs[128 * 32 + c];
    float sgn  = (k1 & 1) ? -1.0f : 1.0f;   // (-1)^{k1} == (-1)^{k2}
    float base = v0 + sgn * v128;
    float re1 = base, im1 = 0.0f;
    float re2 = base, im2 = 0.0f;

    int i1 = 0, i2 = 0;
#pragma unroll 4
    for (int xp = 1; xp <= 127; xp++) {
        i1 = (i1 + k1) & 255;
        i2 = (i2 + k2) & 255;
        float sv = xs[xp * 32 + c];
        float dv = xs[(256 - xp) * 32 + c];
        re1 = fmaf(sv,  ctab[i1], re1);
        im1 = fmaf(-dv, stab[i1], im1);
        re2 = fmaf(sv,  ctab[i2], re2);
        im2 = fmaf(-dv, stab[i2], im2);
    }

    int b = bid >> 8, y = bid & 255;
    g_X1[((b * 16 + k1) * 256 + y) * 32 + c] = make_float2(re1, im1);
    g_X1[((b * 16 + k2) * 256 + y) * 32 + c] = make_float2(re2, im2);
}

// ---------------------------------------------------------------------------
// Kernel 2: per (b,k):  forward H-DFT (32 kept modes) -> einsum -> inverse H.
//   Writes g_G[b][y][k][o] = c_k/(H*W) * sum_{h in S} OB[h][o] e^{+2*pi*i*h*y/256}
// ---------------------------------------------------------------------------
__global__ void k2_mid() {
    __shared__ float2 X2[32 * 32];      // [h'][c]
    __shared__ float2 OB[32 * 32];      // [h'][o]
    __shared__ float2 Ssh[17 * 32];     // [p][o]
    __shared__ float2 Dsh[17 * 32];
    __shared__ float ctab[256], stab[256];

    int t = threadIdx.x;
    int b = blockIdx.x >> 4;
    int k = blockIdx.x & 15;

    {
        float ang = 6.28318530717958647692f * (float)t / 256.0f;
        float s, c0;
        sincosf(ang, &s, &c0);
        ctab[t] = c0; stab[t] = s;
    }
    __syncthreads();

    // --- Step A: P_m,Q_m over y (m = 0..16), streamed from global (L1 reuse) ---
    const float2* __restrict__ xv = g_X1 + (size_t)(b * 16 + k) * 256 * 32; // [y][c]
    for (int tt = t; tt < 17 * 32; tt += 256) {
        int m = tt >> 5, cc = tt & 31;
        float Pr = 0.f, Pi = 0.f, Qr = 0.f, Qi = 0.f;
        int idx = 0;
#pragma unroll 4
        for (int y = 0; y < 256; y++) {
            float2 v = xv[y * 32 + cc];
            float cs = ctab[idx], sn = stab[idx];
            idx = (idx + m) & 255;
            Pr = fmaf(v.x, cs, Pr);
            Pi = fmaf(v.y, cs, Pi);
            Qr = fmaf(v.x, sn, Qr);
            Qi = fmaf(v.y, sn, Qi);
        }
        // map to the 32 kept modes:
        //  h' = m (0..15):        X2 = P - iQ
        //  h' = 32-m (17..31):    X2 = P + iQ   (m = 1..15)
        //  h' = 16 (h=240, m=16): X2 = P + iQ
        if (m == 0) {
            X2[0 * 32 + cc] = make_float2(Pr + Qi, Pi - Qr);
        } else if (m == 16) {
            X2[16 * 32 + cc] = make_float2(Pr - Qi, Pi + Qr);
        } else {
            X2[m * 32 + cc]        = make_float2(Pr + Qi, Pi - Qr);
            X2[(32 - m) * 32 + cc] = make_float2(Pr - Qi, Pi + Qr);
        }
    }
    __syncthreads();

    // --- Step B: einsum over c:  OB[h'][o] = sum_c X2[h'][c] * Wt[k][h'][c][o] ---
    const float2* __restrict__ wtk = g_Wt + (size_t)k * 32 * 32 * 32;
    for (int tt = t; tt < 1024; tt += 256) {
        int hp = tt >> 5, o = tt & 31;
        const float2* __restrict__ wrow = wtk + hp * 1024 + o;   // stride 32 (float2)
        const float2* __restrict__ xrow = X2 + hp * 32;
        float ar = 0.f, ai = 0.f;
#pragma unroll 8
        for (int cc = 0; cc < 32; cc++) {
            float2 xx = xrow[cc];
            float2 ww = wrow[cc * 32];
            ar = fmaf(xx.x, ww.x, ar); ar = fmaf(-xx.y, ww.y, ar);
            ai = fmaf(xx.x, ww.y, ai); ai = fmaf( xx.y, ww.x, ai);
        }
        OB[hp * 32 + o] = make_float2(ar, ai);
    }
    __syncthreads();

    // --- Step C: pair-combine for inverse H:  p=0..16 ---
    //  pair (h=p, h=256-p): S = OB[p]+OB[32-p], D = OB[p]-OB[32-p]
    //  p=0  (h=0):   S=OB0, D=-OB0 (sin term exactly 0)
    //  p=16 (h=240): e^{+2 pi i 240 y/256} = e^{-i * (2 pi 16 y/256)} -> S=OB16, D=-OB16
    for (int tt = t; tt < 17 * 32; tt += 256) {
        int p = tt >> 5, o = tt & 31;
        float2 A = OB[p * 32 + o];
        float2 S, Dd;
        if (p == 0 || p == 16) {
            S = A; Dd = make_float2(-A.x, -A.y);
        } else {
            float2 Bv = OB[(32 - p) * 32 + o];
            S  = make_float2(A.x + Bv.x, A.y + Bv.y);
            Dd = make_float2(A.x - Bv.x, A.y - Bv.y);
        }
        Ssh[p * 32 + o] = S;
        Dsh[p * 32 + o] = Dd;
    }
    __syncthreads();

    // --- Step D: inverse-H to all 256 y, scaled write of g_G ---
    float sc = (k == 0) ? (1.0f / 65536.0f) : (2.0f / 65536.0f);
    int o  = t & 31;
    int yb = t >> 5;    // warp-uniform
#pragma unroll 4
    for (int j = 0; j < 32; j++) {
        int y = yb + 8 * j;
        float gr = 0.f, gi = 0.f;
        int idx = 0;
#pragma unroll
        for (int p = 0; p <= 16; p++) {
            float cs = ctab[idx], sn = stab[idx];
            idx = (idx + y) & 255;
            float2 S  = Ssh[p * 32 + o];
            float2 Dd = Dsh[p * 32 + o];
            gr = fmaf(S.x, cs, gr); gr = fmaf(-Dd.y, sn, gr);
            gi = fmaf(S.y, cs, gi); gi = fmaf( Dd.x, sn, gi);
        }
        g_G[((size_t)(b * 256 + y) * 16 + k) * 32 + o] = make_float2(gr * sc, gi * sc);
    }
}

// ---------------------------------------------------------------------------
// Kernel 3: inverse W per (b,y) row; writes channels_last output.
//   out[x]     = A - B,  out[256-x] = A + B
//   A = sum_k Gr[k] cos(2 pi k x/256),  B = sum_k Gi[k] sin(...)
// ---------------------------------------------------------------------------
__global__ void k3_inv_w(float* __restrict__ out) {
    __shared__ float ctab[256], stab[256];
    int t = threadIdx.x;
    {
        float ang = 6.28318530717958647692f * (float)t / 256.0f;
        float s, c0;
        sincosf(ang, &s, &c0);
        ctab[t] = c0; stab[t] = s;
    }
    __syncthreads();

    int bid = blockIdx.x;                         // b*256 + y
    const float2* __restrict__ g = g_G + (size_t)bid * (KK * CC);
    int o = t & 31;
    int w = t >> 5;                               // warp id, uniform

    float Gr[16], Gi[16];
#pragma unroll
    for (int k = 0; k < 16; k++) {
        float2 v = g[k * 32 + o];                 // coalesced per k
        Gr[k] = v.x; Gi[k] = v.y;
    }

    float* __restrict__ ob = out + (size_t)bid * (WW * CC);
    for (int xp = w; xp <= 128; xp += 8) {
        float A = 0.f, B = 0.f;
        int idx = 0;
#pragma unroll
        for (int k = 0; k < 16; k++) {
            float cs = ctab[idx], sn = stab[idx];
            idx = (idx + xp) & 255;
            A = fmaf(Gr[k], cs, A);
            B = fmaf(Gi[k], sn, B);
        }
        ob[xp * 32 + o] = A - B;
        if (xp != 0 && xp != 128)
            ob[(256 - xp) * 32 + o] = A + B;
    }
}

// ---------------------------------------------------------------------------
extern "C" void kernel_launch(void* const* d_in, const int* in_sizes, int n_in,
                              void* d_out, int out_size) {
    const float* x  = (const float*)d_in[0];
    const float* wr = (const float*)d_in[1];
    const float* wi = (const float*)d_in[2];
    float* out = (float*)d_out;

    k0_reorder_w<<<2048, 256>>>(wr, wi);
    k1_fwd_w   <<<BB * HH, 256>>>(x);
    k2_mid     <<<BB * KK, 256>>>();
    k3_inv_w   <<<BB * HH, 256>>>(out);
}